// round 4
// baseline (speedup 1.0000x reference)
#include <cuda_runtime.h>

typedef unsigned long long u64;

#define NTHREADS 128
#define NBLOCKS  (148 * 2)

// ---------------- packed f32x2 helpers (sm_103a) ----------------
__device__ __forceinline__ u64 fma2(u64 a, u64 b, u64 c) {
    u64 d;
    asm("fma.rn.f32x2 %0, %1, %2, %3;" : "=l"(d) : "l"(a), "l"(b), "l"(c));
    return d;
}
__device__ __forceinline__ u64 add2(u64 a, u64 b) {
    u64 d;
    asm("add.rn.f32x2 %0, %1, %2;" : "=l"(d) : "l"(a), "l"(b));
    return d;
}
__device__ __forceinline__ u64 pack2(float lo, float hi) {
    u64 d;
    asm("mov.b64 %0, {%1, %2};" : "=l"(d) : "f"(lo), "f"(hi));
    return d;
}
__device__ __forceinline__ void unpack2(u64 v, float& lo, float& hi) {
    asm("mov.b64 {%0, %1}, %2;" : "=f"(lo), "=f"(hi) : "l"(v));
}
__device__ __forceinline__ u64 bcast(float x) { return pack2(x, x); }
__device__ __forceinline__ u64 lds64(const float* p) {
    return *reinterpret_cast<const u64*>(p);
}

// ---------------- fast activations (accurate to ~1e-6 rel) ----------------
__device__ __forceinline__ float sigf(float x) {
    float e = __expf(-x);
    return __fdividef(1.0f, 1.0f + e);
}
__device__ __forceinline__ float tanhfast(float x) {
    float e = __expf(-2.0f * x);
    return __fdividef(2.0f, 1.0f + e) - 1.0f;
}

// SMEM layout (floats): offsets even (8B-aligned for LDS.64)
#define OFF_W2T   0        // 64*128 = 8192, [j][k]
#define OFF_W1T   8192     // 20*128 = 2560, [i][j]
#define OFF_W3T   10752    // 64*32  = 2048, [k][m]
#define OFF_B1    12800    // 128
#define OFF_B2    12928    // 64
#define OFF_B3    12992    // 32
#define OFF_W4    13024    // 32
#define OFF_WIH   13056    // 32 (8x4)
#define OFF_WHH   13088    // 16 (8x2)
#define OFF_BIAS  13104    // 8  (b_ih + b_hh)
#define OFF_B4    13112    // 1
#define SMEM_FLOATS 13120
#define SMEM_BYTES  (SMEM_FLOATS * 4)

__global__ void __launch_bounds__(NTHREADS, 2)
lstm_mlp_fused_kernel(const float* __restrict__ x,
                      const float* __restrict__ W_ih, const float* __restrict__ W_hh,
                      const float* __restrict__ b_ih, const float* __restrict__ b_hh,
                      const float* __restrict__ W1, const float* __restrict__ b1,
                      const float* __restrict__ W2, const float* __restrict__ b2,
                      const float* __restrict__ W3, const float* __restrict__ b3,
                      const float* __restrict__ W4, const float* __restrict__ b4,
                      float* __restrict__ out, int n)
{
    extern __shared__ float sm[];
    float* sW2t  = sm + OFF_W2T;
    float* sW1t  = sm + OFF_W1T;
    float* sW3t  = sm + OFF_W3T;
    float* sB1   = sm + OFF_B1;
    float* sB2   = sm + OFF_B2;
    float* sB3   = sm + OFF_B3;
    float* sW4   = sm + OFF_W4;
    float* sWih  = sm + OFF_WIH;
    float* sWhh  = sm + OFF_WHH;
    float* sBias = sm + OFF_BIAS;
    float* sB4   = sm + OFF_B4;

    const int tid = threadIdx.x;

    // ---- stage + transpose weights into SMEM (once per CTA) ----
    for (int idx = tid; idx < 20 * 128; idx += NTHREADS) {
        int i = idx >> 7, j = idx & 127;
        sW1t[idx] = W1[j * 20 + i];
    }
    for (int idx = tid; idx < 64 * 128; idx += NTHREADS) {
        int j = idx >> 6, k = idx & 63;
        sW2t[idx] = W2[k * 128 + j];
    }
    for (int idx = tid; idx < 64 * 32; idx += NTHREADS) {
        int k = idx >> 5, m = idx & 31;
        sW3t[idx] = W3[m * 64 + k];
    }
    if (tid < 128) sB1[tid] = b1[tid];
    if (tid < 64)  sB2[tid] = b2[tid];
    if (tid < 32)  { sB3[tid] = b3[tid]; sW4[tid] = W4[tid]; }
    if (tid < 32)  sWih[tid] = W_ih[tid];
    if (tid < 16)  sWhh[tid] = W_hh[tid];
    if (tid < 8)   sBias[tid] = b_ih[tid] + b_hh[tid];
    if (tid == 0)  sB4[0] = b4[0];
    __syncthreads();

    // Hoist LSTM weights to registers (dead before MLP register peak)
    float rwih[32], rwhh[16], rbias[8];
#pragma unroll
    for (int i = 0; i < 32; i++) rwih[i] = sWih[i];
#pragma unroll
    for (int i = 0; i < 16; i++) rwhh[i] = sWhh[i];
#pragma unroll
    for (int i = 0; i < 8; i++)  rbias[i] = sBias[i];

    const int half = (n + 1) >> 1;
    const int stride = gridDim.x * NTHREADS;
    for (int p = blockIdx.x * NTHREADS + tid; p < half; p += stride) {
        const int b0 = p;
        const int b1 = p + half;
        const bool has_b1 = (b1 < n);
        const int b1c = has_b1 ? b1 : b0;

        // ---- prefetch x for both elements (batched LDG.128 front) ----
        float4 xa4[10], xb4[10];
        {
            const float4* pa = reinterpret_cast<const float4*>(x + (size_t)b0 * 40);
            const float4* pb = reinterpret_cast<const float4*>(x + (size_t)b1c * 40);
#pragma unroll
            for (int t = 0; t < 10; t++) { xa4[t] = pa[t]; xb4[t] = pb[t]; }
        }

        // ================= LSTM for both elements (scalar fp32) =================
        float h0a = 0.f, h1a = 0.f, c0a = 0.f, c1a = 0.f;
        float h0b = 0.f, h1b = 0.f, c0b = 0.f, c1b = 0.f;
        u64 hb0[20], hb1[20];
#pragma unroll
        for (int t = 0; t < 10; t++) {
            float4 xta = xa4[t];
            float4 xtb = xb4[t];
            float gxa[8], gxb[8];   // x-projection: independent of recurrence
#pragma unroll
            for (int gi = 0; gi < 8; gi++) {
                float a = rbias[gi];
                a = fmaf(xta.x, rwih[gi * 4 + 0], a);
                a = fmaf(xta.y, rwih[gi * 4 + 1], a);
                a = fmaf(xta.z, rwih[gi * 4 + 2], a);
                a = fmaf(xta.w, rwih[gi * 4 + 3], a);
                gxa[gi] = a;
                float bvv = rbias[gi];
                bvv = fmaf(xtb.x, rwih[gi * 4 + 0], bvv);
                bvv = fmaf(xtb.y, rwih[gi * 4 + 1], bvv);
                bvv = fmaf(xtb.z, rwih[gi * 4 + 2], bvv);
                bvv = fmaf(xtb.w, rwih[gi * 4 + 3], bvv);
                gxb[gi] = bvv;
            }
            float ga[8], gb[8];
#pragma unroll
            for (int gi = 0; gi < 8; gi++) {
                ga[gi] = fmaf(h1a, rwhh[gi * 2 + 1], fmaf(h0a, rwhh[gi * 2 + 0], gxa[gi]));
                gb[gi] = fmaf(h1b, rwhh[gi * 2 + 1], fmaf(h0b, rwhh[gi * 2 + 0], gxb[gi]));
            }
            float i0a = sigf(ga[0]),     i1a = sigf(ga[1]);
            float f0a = sigf(ga[2]),     f1a = sigf(ga[3]);
            float g0a = tanhfast(ga[4]), g1a = tanhfast(ga[5]);
            float o0a = sigf(ga[6]),     o1a = sigf(ga[7]);
            float i0b = sigf(gb[0]),     i1b = sigf(gb[1]);
            float f0b = sigf(gb[2]),     f1b = sigf(gb[3]);
            float g0b = tanhfast(gb[4]), g1b = tanhfast(gb[5]);
            float o0b = sigf(gb[6]),     o1b = sigf(gb[7]);
            c0a = fmaf(f0a, c0a, i0a * g0a);
            c1a = fmaf(f1a, c1a, i1a * g1a);
            c0b = fmaf(f0b, c0b, i0b * g0b);
            c1b = fmaf(f1b, c1b, i1b * g1b);
            h0a = o0a * tanhfast(c0a);
            h1a = o1a * tanhfast(c1a);
            h0b = o0b * tanhfast(c0b);
            h1b = o1b * tanhfast(c1b);
            hb0[2 * t]     = bcast(h0a);
            hb0[2 * t + 1] = bcast(h1a);
            hb1[2 * t]     = bcast(h0b);
            hb1[2 * t + 1] = bcast(h1b);
        }

        // ============ MLP layer1(20->128) fused into layer2(128->64) ============
        u64 acc2a[32], acc2b[32];
#pragma unroll
        for (int k2 = 0; k2 < 32; k2++) {
            u64 bb = lds64(&sB2[2 * k2]);
            acc2a[k2] = bb;
            acc2b[k2] = bb;
        }

#pragma unroll 2
        for (int jp = 0; jp < 64; jp++) {           // neuron pair (2jp, 2jp+1)
            const float* w1p = &sW1t[2 * jp];
            // 4 independent partial chains per element (depth 20 -> 5)
            u64 aA0 = lds64(&sB1[2 * jp]), aA1 = 0ULL, aA2 = 0ULL, aA3 = 0ULL;
            u64 aB0 = aA0,                 aB1 = 0ULL, aB2 = 0ULL, aB3 = 0ULL;
#pragma unroll
            for (int i = 0; i < 20; i += 4) {
                u64 w0 = lds64(w1p + (i + 0) * 128);
                u64 w1w = lds64(w1p + (i + 1) * 128);
                u64 w2w = lds64(w1p + (i + 2) * 128);
                u64 w3w = lds64(w1p + (i + 3) * 128);
                aA0 = fma2(hb0[i + 0], w0, aA0);
                aB0 = fma2(hb1[i + 0], w0, aB0);
                aA1 = fma2(hb0[i + 1], w1w, aA1);
                aB1 = fma2(hb1[i + 1], w1w, aB1);
                aA2 = fma2(hb0[i + 2], w2w, aA2);
                aB2 = fma2(hb1[i + 2], w2w, aB2);
                aA3 = fma2(hb0[i + 3], w3w, aA3);
                aB3 = fma2(hb1[i + 3], w3w, aB3);
            }
            u64 aA = add2(add2(aA0, aA1), add2(aA2, aA3));
            u64 aB = add2(add2(aB0, aB1), add2(aB2, aB3));

            float a0a, a1a, a0b, a1b;
            unpack2(aA, a0a, a1a);
            unpack2(aB, a0b, a1b);
            u64 v0a = bcast(fmaxf(a0a, 0.f));
            u64 v1a = bcast(fmaxf(a1a, 0.f));
            u64 v0b = bcast(fmaxf(a0b, 0.f));
            u64 v1b = bcast(fmaxf(a1b, 0.f));

            const float* w0p = &sW2t[(2 * jp) * 64];
            const float* w1q = w0p + 64;
#pragma unroll
            for (int k = 0; k < 32; k++) {
                u64 w = lds64(w0p + 2 * k);
                acc2a[k] = fma2(v0a, w, acc2a[k]);
                acc2b[k] = fma2(v0b, w, acc2b[k]);
            }
#pragma unroll
            for (int k = 0; k < 32; k++) {
                u64 w = lds64(w1q + 2 * k);
                acc2a[k] = fma2(v1a, w, acc2a[k]);
                acc2b[k] = fma2(v1b, w, acc2b[k]);
            }
        }

        // ============ layer3 (64->32) ============
        u64 acc3a[16], acc3b[16];
#pragma unroll
        for (int m = 0; m < 16; m++) {
            u64 bb = lds64(&sB3[2 * m]);
            acc3a[m] = bb;
            acc3b[m] = bb;
        }
#pragma unroll 2
        for (int kp = 0; kp < 32; kp++) {
            float s0a, s1a, s0b, s1b;
            unpack2(acc2a[kp], s0a, s1a);
            unpack2(acc2b[kp], s0b, s1b);
            u64 u0a = bcast(fmaxf(s0a, 0.f));
            u64 u1a = bcast(fmaxf(s1a, 0.f));
            u64 u0b = bcast(fmaxf(s0b, 0.f));
            u64 u1b = bcast(fmaxf(s1b, 0.f));
            const float* w0 = &sW3t[(2 * kp) * 32];
            const float* w1 = w0 + 32;
#pragma unroll
            for (int m = 0; m < 16; m++) {
                u64 w = lds64(w0 + 2 * m);
                acc3a[m] = fma2(u0a, w, acc3a[m]);
                acc3b[m] = fma2(u0b, w, acc3b[m]);
            }
#pragma unroll
            for (int m = 0; m < 16; m++) {
                u64 w = lds64(w1 + 2 * m);
                acc3a[m] = fma2(u1a, w, acc3a[m]);
                acc3b[m] = fma2(u1b, w, acc3b[m]);
            }
        }

        // ============ layer4 (32->1), scalar ============
        float oa = sB4[0];
        float ob = oa;
#pragma unroll
        for (int mp = 0; mp < 16; mp++) {
            u64 wp = lds64(&sW4[2 * mp]);
            float w0s, w1s;
            unpack2(wp, w0s, w1s);
            float t0a, t1a, t0b, t1b;
            unpack2(acc3a[mp], t0a, t1a);
            unpack2(acc3b[mp], t0b, t1b);
            oa = fmaf(fmaxf(t0a, 0.f), w0s, oa);
            oa = fmaf(fmaxf(t1a, 0.f), w1s, oa);
            ob = fmaf(fmaxf(t0b, 0.f), w0s, ob);
            ob = fmaf(fmaxf(t1b, 0.f), w1s, ob);
        }
        out[b0] = oa;
        if (has_b1) out[b1] = ob;
    }
}

extern "C" void kernel_launch(void* const* d_in, const int* in_sizes, int n_in,
                              void* d_out, int out_size)
{
    const float* x    = (const float*)d_in[0];
    const float* W_ih = (const float*)d_in[1];
    const float* W_hh = (const float*)d_in[2];
    const float* b_ih = (const float*)d_in[3];
    const float* b_hh = (const float*)d_in[4];
    const float* W1   = (const float*)d_in[5];
    const float* b1   = (const float*)d_in[6];
    const float* W2   = (const float*)d_in[7];
    const float* b2   = (const float*)d_in[8];
    const float* W3   = (const float*)d_in[9];
    const float* b3   = (const float*)d_in[10];
    const float* W4   = (const float*)d_in[11];
    const float* b4   = (const float*)d_in[12];
    float* out = (float*)d_out;

    static bool attr_set = false;
    if (!attr_set) {
        cudaFuncSetAttribute(lstm_mlp_fused_kernel,
                             cudaFuncAttributeMaxDynamicSharedMemorySize, SMEM_BYTES);
        attr_set = true;
    }

    lstm_mlp_fused_kernel<<<NBLOCKS, NTHREADS, SMEM_BYTES>>>(
        x, W_ih, W_hh, b_ih, b_hh, W1, b1, W2, b2, W3, b3, W4, b4,
        out, out_size);
}

// round 5
// speedup vs baseline: 2.0056x; 2.0056x over previous
#include <cuda_runtime.h>

typedef unsigned long long u64;

#define NTHREADS 128
#define NBLOCKS  (148 * 2)

// ---------------- packed f32x2 helpers (sm_103a) ----------------
__device__ __forceinline__ u64 fma2(u64 a, u64 b, u64 c) {
    u64 d;
    asm("fma.rn.f32x2 %0, %1, %2, %3;" : "=l"(d) : "l"(a), "l"(b), "l"(c));
    return d;
}
__device__ __forceinline__ u64 add2(u64 a, u64 b) {
    u64 d;
    asm("add.rn.f32x2 %0, %1, %2;" : "=l"(d) : "l"(a), "l"(b));
    return d;
}
__device__ __forceinline__ u64 pack2(float lo, float hi) {
    u64 d;
    asm("mov.b64 %0, {%1, %2};" : "=l"(d) : "f"(lo), "f"(hi));
    return d;
}
__device__ __forceinline__ void unpack2(u64 v, float& lo, float& hi) {
    asm("mov.b64 {%0, %1}, %2;" : "=f"(lo), "=f"(hi) : "l"(v));
}
__device__ __forceinline__ u64 bcast(float x) { return pack2(x, x); }
__device__ __forceinline__ u64 lds64(const float* p) {
    return *reinterpret_cast<const u64*>(p);
}

// ---------------- fast activations (accurate to ~1e-6 rel) ----------------
__device__ __forceinline__ float sigf(float x) {
    float e = __expf(-x);
    return __fdividef(1.0f, 1.0f + e);
}
__device__ __forceinline__ float tanhfast(float x) {
    float e = __expf(-2.0f * x);
    return __fdividef(2.0f, 1.0f + e) - 1.0f;
}

// SMEM layout (floats): offsets even (8B-aligned for LDS.64)
#define OFF_W2T   0        // 64*128 = 8192, [j][k]
#define OFF_W1T   8192     // 20*128 = 2560, [i][j]
#define OFF_W3T   10752    // 64*32  = 2048, [k][m]
#define OFF_B1    12800    // 128
#define OFF_B2    12928    // 64
#define OFF_B3    12992    // 32
#define OFF_W4    13024    // 32
#define OFF_WIH   13056    // 32 (8x4)
#define OFF_WHH   13088    // 16 (8x2)
#define OFF_BIAS  13104    // 8  (b_ih + b_hh)
#define OFF_B4    13112    // 1
#define SMEM_FLOATS 13120
#define SMEM_BYTES  (SMEM_FLOATS * 4)

__global__ void __launch_bounds__(NTHREADS, 2)
lstm_mlp_fused_kernel(const float* __restrict__ x,
                      const float* __restrict__ W_ih, const float* __restrict__ W_hh,
                      const float* __restrict__ b_ih, const float* __restrict__ b_hh,
                      const float* __restrict__ W1, const float* __restrict__ b1,
                      const float* __restrict__ W2, const float* __restrict__ b2,
                      const float* __restrict__ W3, const float* __restrict__ b3,
                      const float* __restrict__ W4, const float* __restrict__ b4,
                      float* __restrict__ out, int n)
{
    extern __shared__ float sm[];
    float* sW2t  = sm + OFF_W2T;
    float* sW1t  = sm + OFF_W1T;
    float* sW3t  = sm + OFF_W3T;
    float* sB1   = sm + OFF_B1;
    float* sB2   = sm + OFF_B2;
    float* sB3   = sm + OFF_B3;
    float* sW4   = sm + OFF_W4;
    float* sWih  = sm + OFF_WIH;
    float* sWhh  = sm + OFF_WHH;
    float* sBias = sm + OFF_BIAS;
    float* sB4   = sm + OFF_B4;

    const int tid = threadIdx.x;

    // ---- stage + transpose weights into SMEM (once per CTA) ----
    for (int idx = tid; idx < 20 * 128; idx += NTHREADS) {
        int i = idx >> 7, j = idx & 127;
        sW1t[idx] = W1[j * 20 + i];
    }
    for (int idx = tid; idx < 64 * 128; idx += NTHREADS) {
        int j = idx >> 6, k = idx & 63;
        sW2t[idx] = W2[k * 128 + j];
    }
    for (int idx = tid; idx < 64 * 32; idx += NTHREADS) {
        int k = idx >> 5, m = idx & 31;
        sW3t[idx] = W3[m * 64 + k];
    }
    if (tid < 128) sB1[tid] = b1[tid];
    if (tid < 64)  sB2[tid] = b2[tid];
    if (tid < 32)  { sB3[tid] = b3[tid]; sW4[tid] = W4[tid]; }
    if (tid < 32)  sWih[tid] = W_ih[tid];
    if (tid < 16)  sWhh[tid] = W_hh[tid];
    if (tid < 8)   sBias[tid] = b_ih[tid] + b_hh[tid];
    if (tid == 0)  sB4[0] = b4[0];
    __syncthreads();

    // Hoist LSTM weights to registers (dead before MLP register peak)
    float rwih[32], rwhh[16], rbias[8];
#pragma unroll
    for (int i = 0; i < 32; i++) rwih[i] = sWih[i];
#pragma unroll
    for (int i = 0; i < 16; i++) rwhh[i] = sWhh[i];
#pragma unroll
    for (int i = 0; i < 8; i++)  rbias[i] = sBias[i];

    const int half = (n + 1) >> 1;
    const int stride = gridDim.x * NTHREADS;
    for (int p = blockIdx.x * NTHREADS + tid; p < half; p += stride) {
        const int b0 = p;
        const int b1 = p + half;
        const bool has_b1 = (b1 < n);
        const int b1c = has_b1 ? b1 : b0;

        // ================= LSTM for both elements (scalar fp32) =================
        float h0a = 0.f, h1a = 0.f, c0a = 0.f, c1a = 0.f;
        float h0b = 0.f, h1b = 0.f, c0b = 0.f, c1b = 0.f;
        u64 hb0[20], hb1[20];
        const float* xa = x + (size_t)b0 * 40;
        const float* xb = x + (size_t)b1c * 40;
#pragma unroll
        for (int t = 0; t < 10; t++) {
            float4 xta = *reinterpret_cast<const float4*>(xa + t * 4);
            float4 xtb = *reinterpret_cast<const float4*>(xb + t * 4);
            float ga[8], gb[8];
#pragma unroll
            for (int gi = 0; gi < 8; gi++) {
                float a = rbias[gi];
                a = fmaf(xta.x, rwih[gi * 4 + 0], a);
                a = fmaf(xta.y, rwih[gi * 4 + 1], a);
                a = fmaf(xta.z, rwih[gi * 4 + 2], a);
                a = fmaf(xta.w, rwih[gi * 4 + 3], a);
                a = fmaf(h0a, rwhh[gi * 2 + 0], a);
                a = fmaf(h1a, rwhh[gi * 2 + 1], a);
                ga[gi] = a;
                float bvv = rbias[gi];
                bvv = fmaf(xtb.x, rwih[gi * 4 + 0], bvv);
                bvv = fmaf(xtb.y, rwih[gi * 4 + 1], bvv);
                bvv = fmaf(xtb.z, rwih[gi * 4 + 2], bvv);
                bvv = fmaf(xtb.w, rwih[gi * 4 + 3], bvv);
                bvv = fmaf(h0b, rwhh[gi * 2 + 0], bvv);
                bvv = fmaf(h1b, rwhh[gi * 2 + 1], bvv);
                gb[gi] = bvv;
            }
            float i0a = sigf(ga[0]),     i1a = sigf(ga[1]);
            float f0a = sigf(ga[2]),     f1a = sigf(ga[3]);
            float g0a = tanhfast(ga[4]), g1a = tanhfast(ga[5]);
            float o0a = sigf(ga[6]),     o1a = sigf(ga[7]);
            float i0b = sigf(gb[0]),     i1b = sigf(gb[1]);
            float f0b = sigf(gb[2]),     f1b = sigf(gb[3]);
            float g0b = tanhfast(gb[4]), g1b = tanhfast(gb[5]);
            float o0b = sigf(gb[6]),     o1b = sigf(gb[7]);
            c0a = fmaf(f0a, c0a, i0a * g0a);
            c1a = fmaf(f1a, c1a, i1a * g1a);
            c0b = fmaf(f0b, c0b, i0b * g0b);
            c1b = fmaf(f1b, c1b, i1b * g1b);
            h0a = o0a * tanhfast(c0a);
            h1a = o1a * tanhfast(c1a);
            h0b = o0b * tanhfast(c0b);
            h1b = o1b * tanhfast(c1b);
            hb0[2 * t]     = bcast(h0a);
            hb0[2 * t + 1] = bcast(h1a);
            hb1[2 * t]     = bcast(h0b);
            hb1[2 * t + 1] = bcast(h1b);
        }

        // ============ MLP layer1(20->128) fused into layer2(128->64) ============
        // Lanes of f32x2 = neuron pairs; one weight LDS feeds BOTH elements.
        u64 acc2a[32], acc2b[32];
#pragma unroll
        for (int k2 = 0; k2 < 32; k2++) {
            u64 bb = lds64(&sB2[2 * k2]);
            acc2a[k2] = bb;
            acc2b[k2] = bb;
        }

#pragma unroll 1
        for (int jp = 0; jp < 64; jp++) {           // neuron pair (2jp, 2jp+1)
            const float* w1p = &sW1t[2 * jp];
            // 2 independent partial chains per element (depth 20 -> 10)
            u64 aA0 = lds64(&sB1[2 * jp]), aA1 = 0ULL;
            u64 aB0 = aA0,                 aB1 = 0ULL;
#pragma unroll
            for (int i = 0; i < 20; i += 2) {
                u64 w0 = lds64(w1p + (i + 0) * 128);
                u64 w1w = lds64(w1p + (i + 1) * 128);
                aA0 = fma2(hb0[i + 0], w0, aA0);
                aB0 = fma2(hb1[i + 0], w0, aB0);
                aA1 = fma2(hb0[i + 1], w1w, aA1);
                aB1 = fma2(hb1[i + 1], w1w, aB1);
            }
            u64 aA = add2(aA0, aA1);
            u64 aB = add2(aB0, aB1);

            float a0a, a1a, a0b, a1b;
            unpack2(aA, a0a, a1a);
            unpack2(aB, a0b, a1b);
            u64 v0a = bcast(fmaxf(a0a, 0.f));
            u64 v1a = bcast(fmaxf(a1a, 0.f));
            u64 v0b = bcast(fmaxf(a0b, 0.f));
            u64 v1b = bcast(fmaxf(a1b, 0.f));

            const float* w0p = &sW2t[(2 * jp) * 64];
            const float* w1q = w0p + 64;
            // merged k-loop: two independent LDS streams per iteration
#pragma unroll
            for (int k = 0; k < 32; k++) {
                u64 wa = lds64(w0p + 2 * k);
                u64 wb = lds64(w1q + 2 * k);
                u64 ta = fma2(v0a, wa, acc2a[k]);
                u64 tb = fma2(v0b, wa, acc2b[k]);
                acc2a[k] = fma2(v1a, wb, ta);
                acc2b[k] = fma2(v1b, wb, tb);
            }
        }

        // ============ layer3 (64->32) ============
        u64 acc3a[16], acc3b[16];
#pragma unroll
        for (int m = 0; m < 16; m++) {
            u64 bb = lds64(&sB3[2 * m]);
            acc3a[m] = bb;
            acc3b[m] = bb;
        }
#pragma unroll 1
        for (int kp = 0; kp < 32; kp++) {
            float s0a, s1a, s0b, s1b;
            unpack2(acc2a[kp], s0a, s1a);
            unpack2(acc2b[kp], s0b, s1b);
            u64 u0a = bcast(fmaxf(s0a, 0.f));
            u64 u1a = bcast(fmaxf(s1a, 0.f));
            u64 u0b = bcast(fmaxf(s0b, 0.f));
            u64 u1b = bcast(fmaxf(s1b, 0.f));
            const float* w0 = &sW3t[(2 * kp) * 32];
            const float* w1 = w0 + 32;
#pragma unroll
            for (int m = 0; m < 16; m++) {
                u64 wa = lds64(w0 + 2 * m);
                u64 wb = lds64(w1 + 2 * m);
                u64 ta = fma2(u0a, wa, acc3a[m]);
                u64 tb = fma2(u0b, wa, acc3b[m]);
                acc3a[m] = fma2(u1a, wb, ta);
                acc3b[m] = fma2(u1b, wb, tb);
            }
        }

        // ============ layer4 (32->1), scalar ============
        float oa = sB4[0];
        float ob = oa;
#pragma unroll
        for (int mp = 0; mp < 16; mp++) {
            u64 wp = lds64(&sW4[2 * mp]);
            float w0s, w1s;
            unpack2(wp, w0s, w1s);
            float t0a, t1a, t0b, t1b;
            unpack2(acc3a[mp], t0a, t1a);
            unpack2(acc3b[mp], t0b, t1b);
            oa = fmaf(fmaxf(t0a, 0.f), w0s, oa);
            oa = fmaf(fmaxf(t1a, 0.f), w1s, oa);
            ob = fmaf(fmaxf(t0b, 0.f), w0s, ob);
            ob = fmaf(fmaxf(t1b, 0.f), w1s, ob);
        }
        out[b0] = oa;
        if (has_b1) out[b1] = ob;
    }
}

extern "C" void kernel_launch(void* const* d_in, const int* in_sizes, int n_in,
                              void* d_out, int out_size)
{
    const float* x    = (const float*)d_in[0];
    const float* W_ih = (const float*)d_in[1];
    const float* W_hh = (const float*)d_in[2];
    const float* b_ih = (const float*)d_in[3];
    const float* b_hh = (const float*)d_in[4];
    const float* W1   = (const float*)d_in[5];
    const float* b1   = (const float*)d_in[6];
    const float* W2   = (const float*)d_in[7];
    const float* b2   = (const float*)d_in[8];
    const float* W3   = (const float*)d_in[9];
    const float* b3   = (const float*)d_in[10];
    const float* W4   = (const float*)d_in[11];
    const float* b4   = (const float*)d_in[12];
    float* out = (float*)d_out;

    static bool attr_set = false;
    if (!attr_set) {
        cudaFuncSetAttribute(lstm_mlp_fused_kernel,
                             cudaFuncAttributeMaxDynamicSharedMemorySize, SMEM_BYTES);
        attr_set = true;
    }

    lstm_mlp_fused_kernel<<<NBLOCKS, NTHREADS, SMEM_BYTES>>>(
        x, W_ih, W_hh, b_ih, b_hh, W1, b1, W2, b2, W3, b3, W4, b4,
        out, out_size);
}

// round 6
// speedup vs baseline: 2.0064x; 1.0004x over previous
#include <cuda_runtime.h>

typedef unsigned long long u64;

#define NTHREADS 128
#define NBLOCKS  (148 * 2)

// ---------------- packed f32x2 helpers (sm_103a) ----------------
__device__ __forceinline__ u64 fma2(u64 a, u64 b, u64 c) {
    u64 d;
    asm("fma.rn.f32x2 %0, %1, %2, %3;" : "=l"(d) : "l"(a), "l"(b), "l"(c));
    return d;
}
__device__ __forceinline__ u64 add2(u64 a, u64 b) {
    u64 d;
    asm("add.rn.f32x2 %0, %1, %2;" : "=l"(d) : "l"(a), "l"(b));
    return d;
}
__device__ __forceinline__ u64 pack2(float lo, float hi) {
    u64 d;
    asm("mov.b64 %0, {%1, %2};" : "=l"(d) : "f"(lo), "f"(hi));
    return d;
}
__device__ __forceinline__ void unpack2(u64 v, float& lo, float& hi) {
    asm("mov.b64 {%0, %1}, %2;" : "=f"(lo), "=f"(hi) : "l"(v));
}
__device__ __forceinline__ u64 bcast(float x) { return pack2(x, x); }
__device__ __forceinline__ u64 lds64(const float* p) {
    return *reinterpret_cast<const u64*>(p);
}

// ---------------- fast activations (accurate to ~1e-6 rel) ----------------
__device__ __forceinline__ float sigf(float x) {
    float e = __expf(-x);
    return __fdividef(1.0f, 1.0f + e);
}
__device__ __forceinline__ float tanhfast(float x) {
    float e = __expf(-2.0f * x);
    return __fdividef(2.0f, 1.0f + e) - 1.0f;
}

// SMEM layout (floats): offsets even (8B-aligned for LDS.64)
#define OFF_W2T   0        // 64*128 = 8192, [j][k]
#define OFF_W1T   8192     // 20*128 = 2560, [i][j]
#define OFF_W3T   10752    // 64*32  = 2048, [k][m]
#define OFF_B1    12800    // 128
#define OFF_B2    12928    // 64
#define OFF_B3    12992    // 32
#define OFF_W4    13024    // 32
#define OFF_WIH   13056    // 32 (8x4)
#define OFF_WHH   13088    // 16 (8x2)
#define OFF_BIAS  13104    // 8  (b_ih + b_hh)
#define OFF_B4    13112    // 1
#define SMEM_FLOATS 13120
#define SMEM_BYTES  (SMEM_FLOATS * 4)

__global__ void __launch_bounds__(NTHREADS, 2)
lstm_mlp_fused_kernel(const float* __restrict__ x,
                      const float* __restrict__ W_ih, const float* __restrict__ W_hh,
                      const float* __restrict__ b_ih, const float* __restrict__ b_hh,
                      const float* __restrict__ W1, const float* __restrict__ b1,
                      const float* __restrict__ W2, const float* __restrict__ b2,
                      const float* __restrict__ W3, const float* __restrict__ b3,
                      const float* __restrict__ W4, const float* __restrict__ b4,
                      float* __restrict__ out, int n)
{
    extern __shared__ float sm[];
    float* sW2t  = sm + OFF_W2T;
    float* sW1t  = sm + OFF_W1T;
    float* sW3t  = sm + OFF_W3T;
    float* sB1   = sm + OFF_B1;
    float* sB2   = sm + OFF_B2;
    float* sB3   = sm + OFF_B3;
    float* sW4   = sm + OFF_W4;
    float* sWih  = sm + OFF_WIH;
    float* sWhh  = sm + OFF_WHH;
    float* sBias = sm + OFF_BIAS;
    float* sB4   = sm + OFF_B4;

    const int tid = threadIdx.x;

    // ---- stage + transpose weights into SMEM (once per CTA) ----
    for (int idx = tid; idx < 20 * 128; idx += NTHREADS) {
        int i = idx >> 7, j = idx & 127;
        sW1t[idx] = W1[j * 20 + i];
    }
    for (int idx = tid; idx < 64 * 128; idx += NTHREADS) {
        int j = idx >> 6, k = idx & 63;
        sW2t[idx] = W2[k * 128 + j];
    }
    for (int idx = tid; idx < 64 * 32; idx += NTHREADS) {
        int k = idx >> 5, m = idx & 31;
        sW3t[idx] = W3[m * 64 + k];
    }
    if (tid < 128) sB1[tid] = b1[tid];
    if (tid < 64)  sB2[tid] = b2[tid];
    if (tid < 32)  { sB3[tid] = b3[tid]; sW4[tid] = W4[tid]; }
    if (tid < 32)  sWih[tid] = W_ih[tid];
    if (tid < 16)  sWhh[tid] = W_hh[tid];
    if (tid < 8)   sBias[tid] = b_ih[tid] + b_hh[tid];
    if (tid == 0)  sB4[0] = b4[0];
    __syncthreads();

    // Hoist LSTM weights to registers (dead before MLP register peak)
    float rwih[32], rwhh[16], rbias[8];
#pragma unroll
    for (int i = 0; i < 32; i++) rwih[i] = sWih[i];
#pragma unroll
    for (int i = 0; i < 16; i++) rwhh[i] = sWhh[i];
#pragma unroll
    for (int i = 0; i < 8; i++)  rbias[i] = sBias[i];

    const int half = (n + 1) >> 1;
    const int stride = gridDim.x * NTHREADS;
    for (int p = blockIdx.x * NTHREADS + tid; p < half; p += stride) {
        const int b0 = p;
        const int b1 = p + half;
        const bool has_b1 = (b1 < n);
        const int b1c = has_b1 ? b1 : b0;

        // ================= LSTM for both elements (scalar fp32) =================
        float h0a = 0.f, h1a = 0.f, c0a = 0.f, c1a = 0.f;
        float h0b = 0.f, h1b = 0.f, c0b = 0.f, c1b = 0.f;
        u64 hb0[20], hb1[20];
        const float* xa = x + (size_t)b0 * 40;
        const float* xb = x + (size_t)b1c * 40;
#pragma unroll
        for (int t = 0; t < 10; t++) {
            float4 xta = *reinterpret_cast<const float4*>(xa + t * 4);
            float4 xtb = *reinterpret_cast<const float4*>(xb + t * 4);
            float ga[8], gb[8];
#pragma unroll
            for (int gi = 0; gi < 8; gi++) {
                float a = rbias[gi];
                a = fmaf(xta.x, rwih[gi * 4 + 0], a);
                a = fmaf(xta.y, rwih[gi * 4 + 1], a);
                a = fmaf(xta.z, rwih[gi * 4 + 2], a);
                a = fmaf(xta.w, rwih[gi * 4 + 3], a);
                a = fmaf(h0a, rwhh[gi * 2 + 0], a);
                a = fmaf(h1a, rwhh[gi * 2 + 1], a);
                ga[gi] = a;
                float bvv = rbias[gi];
                bvv = fmaf(xtb.x, rwih[gi * 4 + 0], bvv);
                bvv = fmaf(xtb.y, rwih[gi * 4 + 1], bvv);
                bvv = fmaf(xtb.z, rwih[gi * 4 + 2], bvv);
                bvv = fmaf(xtb.w, rwih[gi * 4 + 3], bvv);
                bvv = fmaf(h0b, rwhh[gi * 2 + 0], bvv);
                bvv = fmaf(h1b, rwhh[gi * 2 + 1], bvv);
                gb[gi] = bvv;
            }
            float i0a = sigf(ga[0]),     i1a = sigf(ga[1]);
            float f0a = sigf(ga[2]),     f1a = sigf(ga[3]);
            float g0a = tanhfast(ga[4]), g1a = tanhfast(ga[5]);
            float o0a = sigf(ga[6]),     o1a = sigf(ga[7]);
            float i0b = sigf(gb[0]),     i1b = sigf(gb[1]);
            float f0b = sigf(gb[2]),     f1b = sigf(gb[3]);
            float g0b = tanhfast(gb[4]), g1b = tanhfast(gb[5]);
            float o0b = sigf(gb[6]),     o1b = sigf(gb[7]);
            c0a = fmaf(f0a, c0a, i0a * g0a);
            c1a = fmaf(f1a, c1a, i1a * g1a);
            c0b = fmaf(f0b, c0b, i0b * g0b);
            c1b = fmaf(f1b, c1b, i1b * g1b);
            h0a = o0a * tanhfast(c0a);
            h1a = o1a * tanhfast(c1a);
            h0b = o0b * tanhfast(c0b);
            h1b = o1b * tanhfast(c1b);
            hb0[2 * t]     = bcast(h0a);
            hb0[2 * t + 1] = bcast(h1a);
            hb1[2 * t]     = bcast(h0b);
            hb1[2 * t + 1] = bcast(h1b);
        }

        // ============ MLP layer1(20->128) fused into layer2(128->64) ============
        // Lanes of f32x2 = neuron pairs; one weight LDS feeds BOTH elements.
        u64 acc2a[32], acc2b[32];
#pragma unroll
        for (int k2 = 0; k2 < 32; k2++) {
            u64 bb = lds64(&sB2[2 * k2]);
            acc2a[k2] = bb;
            acc2b[k2] = bb;
        }

#pragma unroll 1
        for (int jp = 0; jp < 64; jp++) {           // neuron pair (2jp, 2jp+1)
            const float* w1p = &sW1t[2 * jp];
            // 2 independent partial chains per element (depth 20 -> 10)
            u64 aA0 = lds64(&sB1[2 * jp]), aA1 = 0ULL;
            u64 aB0 = aA0,                 aB1 = 0ULL;
#pragma unroll
            for (int i = 0; i < 20; i += 2) {
                u64 w0 = lds64(w1p + (i + 0) * 128);
                u64 w1w = lds64(w1p + (i + 1) * 128);
                aA0 = fma2(hb0[i + 0], w0, aA0);
                aB0 = fma2(hb1[i + 0], w0, aB0);
                aA1 = fma2(hb0[i + 1], w1w, aA1);
                aB1 = fma2(hb1[i + 1], w1w, aB1);
            }
            u64 aA = add2(aA0, aA1);
            u64 aB = add2(aB0, aB1);

            float a0a, a1a, a0b, a1b;
            unpack2(aA, a0a, a1a);
            unpack2(aB, a0b, a1b);
            u64 v0a = bcast(fmaxf(a0a, 0.f));
            u64 v1a = bcast(fmaxf(a1a, 0.f));
            u64 v0b = bcast(fmaxf(a0b, 0.f));
            u64 v1b = bcast(fmaxf(a1b, 0.f));

            const float* w0p = &sW2t[(2 * jp) * 64];
            const float* w1q = w0p + 64;
            // merged k-loop: two independent LDS streams per iteration
#pragma unroll
            for (int k = 0; k < 32; k++) {
                u64 wa = lds64(w0p + 2 * k);
                u64 wb = lds64(w1q + 2 * k);
                u64 ta = fma2(v0a, wa, acc2a[k]);
                u64 tb = fma2(v0b, wa, acc2b[k]);
                acc2a[k] = fma2(v1a, wb, ta);
                acc2b[k] = fma2(v1b, wb, tb);
            }
        }

        // ============ layer3 (64->32) ============
        u64 acc3a[16], acc3b[16];
#pragma unroll
        for (int m = 0; m < 16; m++) {
            u64 bb = lds64(&sB3[2 * m]);
            acc3a[m] = bb;
            acc3b[m] = bb;
        }
#pragma unroll 1
        for (int kp = 0; kp < 32; kp++) {
            float s0a, s1a, s0b, s1b;
            unpack2(acc2a[kp], s0a, s1a);
            unpack2(acc2b[kp], s0b, s1b);
            u64 u0a = bcast(fmaxf(s0a, 0.f));
            u64 u1a = bcast(fmaxf(s1a, 0.f));
            u64 u0b = bcast(fmaxf(s0b, 0.f));
            u64 u1b = bcast(fmaxf(s1b, 0.f));
            const float* w0 = &sW3t[(2 * kp) * 32];
            const float* w1 = w0 + 32;
#pragma unroll
            for (int m = 0; m < 16; m++) {
                u64 wa = lds64(w0 + 2 * m);
                u64 wb = lds64(w1 + 2 * m);
                u64 ta = fma2(u0a, wa, acc3a[m]);
                u64 tb = fma2(u0b, wa, acc3b[m]);
                acc3a[m] = fma2(u1a, wb, ta);
                acc3b[m] = fma2(u1b, wb, tb);
            }
        }

        // ============ layer4 (32->1), scalar ============
        float oa = sB4[0];
        float ob = oa;
#pragma unroll
        for (int mp = 0; mp < 16; mp++) {
            u64 wp = lds64(&sW4[2 * mp]);
            float w0s, w1s;
            unpack2(wp, w0s, w1s);
            float t0a, t1a, t0b, t1b;
            unpack2(acc3a[mp], t0a, t1a);
            unpack2(acc3b[mp], t0b, t1b);
            oa = fmaf(fmaxf(t0a, 0.f), w0s, oa);
            oa = fmaf(fmaxf(t1a, 0.f), w1s, oa);
            ob = fmaf(fmaxf(t0b, 0.f), w0s, ob);
            ob = fmaf(fmaxf(t1b, 0.f), w1s, ob);
        }
        out[b0] = oa;
        if (has_b1) out[b1] = ob;
    }
}

extern "C" void kernel_launch(void* const* d_in, const int* in_sizes, int n_in,
                              void* d_out, int out_size)
{
    const float* x    = (const float*)d_in[0];
    const float* W_ih = (const float*)d_in[1];
    const float* W_hh = (const float*)d_in[2];
    const float* b_ih = (const float*)d_in[3];
    const float* b_hh = (const float*)d_in[4];
    const float* W1   = (const float*)d_in[5];
    const float* b1   = (const float*)d_in[6];
    const float* W2   = (const float*)d_in[7];
    const float* b2   = (const float*)d_in[8];
    const float* W3   = (const float*)d_in[9];
    const float* b3   = (const float*)d_in[10];
    const float* W4   = (const float*)d_in[11];
    const float* b4   = (const float*)d_in[12];
    float* out = (float*)d_out;

    static bool attr_set = false;
    if (!attr_set) {
        cudaFuncSetAttribute(lstm_mlp_fused_kernel,
                             cudaFuncAttributeMaxDynamicSharedMemorySize, SMEM_BYTES);
        attr_set = true;
    }

    lstm_mlp_fused_kernel<<<NBLOCKS, NTHREADS, SMEM_BYTES>>>(
        x, W_ih, W_hh, b_ih, b_hh, W1, b1, W2, b2, W3, b3, W4, b4,
        out, out_size);
}

// round 8
// speedup vs baseline: 4.2121x; 2.0994x over previous
#include <cuda_runtime.h>
#include <cstdint>

#define NTHREADS 128
#define NBLOCKS  (148 * 2)

// ---------------- SMEM byte offsets ----------------
#define OB_B1H   0        // W1 B-frags hi: 32 frags * 32 lanes * 8B = 8192
#define OB_B1L   8192
#define OB_B2H   16384    // W2: 64 frags = 16384
#define OB_B2L   32768
#define OB_B3H   49152    // W3: 16 frags = 4096
#define OB_B3L   53248
#define OB_HHI   57344    // h hi words: 128 rows * 16 w * 4B = 8192
#define OB_HLO   65536
#define OB_b1    73728    // 128 f
#define OB_b2    74240    // 64 f
#define OB_b3    74496    // 32 f
#define OB_w4    74624    // 32 f
#define OB_b4    74752
#define OB_wih   74768    // 32 f
#define OB_whh   74896    // 16 f
#define OB_bias  74960    // 8 f
#define SMEM_BYTES 75008

// ---------------- helpers ----------------
__device__ __forceinline__ uint32_t bf16rn(float f) {
    uint32_t u = __float_as_uint(f);
    return (u + 0x7FFFu + ((u >> 16) & 1u)) >> 16;
}
// split a,b into hi word (truncated bf16 pair, a in low half) and lo word (rounded residuals)
__device__ __forceinline__ void splitpack(float a, float b, uint32_t& hi, uint32_t& lo) {
    uint32_t ua = __float_as_uint(a), ub = __float_as_uint(b);
    hi = (ub & 0xFFFF0000u) | (ua >> 16);
    float ra = a - __uint_as_float(ua & 0xFFFF0000u);
    float rb = b - __uint_as_float(ub & 0xFFFF0000u);
    lo = (bf16rn(rb) << 16) | bf16rn(ra);
}
__device__ __forceinline__ void mma_bf16(float* c, const uint32_t* a, uint2 b) {
    asm volatile(
        "mma.sync.aligned.m16n8k16.row.col.f32.bf16.bf16.f32 "
        "{%0,%1,%2,%3}, {%4,%5,%6,%7}, {%8,%9}, {%0,%1,%2,%3};"
        : "+f"(c[0]), "+f"(c[1]), "+f"(c[2]), "+f"(c[3])
        : "r"(a[0]), "r"(a[1]), "r"(a[2]), "r"(a[3]), "r"(b.x), "r"(b.y));
}
__device__ __forceinline__ float sigf(float x) {
    float e = __expf(-x);
    return __fdividef(1.0f, 1.0f + e);
}
__device__ __forceinline__ float tanhfast(float x) {
    float e = __expf(-2.0f * x);
    return __fdividef(2.0f, 1.0f + e) - 1.0f;
}

__global__ void __launch_bounds__(NTHREADS, 2)
lstm_mlp_mma_kernel(const float* __restrict__ x,
                    const float* __restrict__ W_ih, const float* __restrict__ W_hh,
                    const float* __restrict__ b_ih, const float* __restrict__ b_hh,
                    const float* __restrict__ W1, const float* __restrict__ b1,
                    const float* __restrict__ W2, const float* __restrict__ b2,
                    const float* __restrict__ W3, const float* __restrict__ b3,
                    const float* __restrict__ W4, const float* __restrict__ b4,
                    float* __restrict__ out, int n)
{
    extern __shared__ char smem[];
    const int tid  = threadIdx.x;
    const int lane = tid & 31;

    uint2* sB1h = (uint2*)(smem + OB_B1H);
    uint2* sB1l = (uint2*)(smem + OB_B1L);
    uint2* sB2h = (uint2*)(smem + OB_B2H);
    uint2* sB2l = (uint2*)(smem + OB_B2L);
    uint2* sB3h = (uint2*)(smem + OB_B3H);
    uint2* sB3l = (uint2*)(smem + OB_B3L);
    uint32_t* hH = (uint32_t*)(smem + OB_HHI);
    uint32_t* hL = (uint32_t*)(smem + OB_HLO);
    float* sb1  = (float*)(smem + OB_b1);
    float* sb2  = (float*)(smem + OB_b2);
    float* sb3  = (float*)(smem + OB_b3);
    float* sw4  = (float*)(smem + OB_w4);
    float* sb4  = (float*)(smem + OB_b4);
    float* sWih = (float*)(smem + OB_wih);
    float* sWhh = (float*)(smem + OB_whh);
    float* sBias= (float*)(smem + OB_bias);

    // ---- stage small params ----
    if (tid < 128) sb1[tid] = b1[tid];
    if (tid < 64)  sb2[tid] = b2[tid];
    if (tid < 32)  { sb3[tid] = b3[tid]; sw4[tid] = W4[tid]; }
    if (tid == 0)  sb4[0] = b4[0];
    if (tid < 32)  sWih[tid] = W_ih[tid];
    if (tid < 16)  sWhh[tid] = W_hh[tid];
    if (tid < 8)   sBias[tid] = b_ih[tid] + b_hh[tid];

    // ---- precompute B fragments (native m16n8k16 col-major B layout) ----
    // W1 [128,20], K padded to 32: 2 kc x 16 nt
    for (int e = tid; e < 32 * 32; e += NTHREADS) {
        int l = e & 31, f = e >> 5;
        int kc = f >> 4, nt = f & 15;
        int col = nt * 8 + (l >> 2);
        int k0 = kc * 16 + (l & 3) * 2;
        float v00 = (k0     < 20) ? W1[col * 20 + k0]     : 0.f;
        float v01 = (k0 + 1 < 20) ? W1[col * 20 + k0 + 1] : 0.f;
        float v10 = (k0 + 8 < 20) ? W1[col * 20 + k0 + 8] : 0.f;
        float v11 = (k0 + 9 < 20) ? W1[col * 20 + k0 + 9] : 0.f;
        uint32_t h0, l0, h1, l1;
        splitpack(v00, v01, h0, l0);
        splitpack(v10, v11, h1, l1);
        sB1h[f * 32 + l] = make_uint2(h0, h1);
        sB1l[f * 32 + l] = make_uint2(l0, l1);
    }
    // W2 [64,128]: 8 kc x 8 nt
    for (int e = tid; e < 64 * 32; e += NTHREADS) {
        int l = e & 31, f = e >> 5;
        int kc = f >> 3, nt = f & 7;
        int col = nt * 8 + (l >> 2);
        int k0 = kc * 16 + (l & 3) * 2;
        uint32_t h0, l0, h1, l1;
        splitpack(W2[col * 128 + k0],     W2[col * 128 + k0 + 1], h0, l0);
        splitpack(W2[col * 128 + k0 + 8], W2[col * 128 + k0 + 9], h1, l1);
        sB2h[f * 32 + l] = make_uint2(h0, h1);
        sB2l[f * 32 + l] = make_uint2(l0, l1);
    }
    // W3 [32,64]: 4 kc x 4 nt
    for (int e = tid; e < 16 * 32; e += NTHREADS) {
        int l = e & 31, f = e >> 5;
        int kc = f >> 2, nt = f & 3;
        int col = nt * 8 + (l >> 2);
        int k0 = kc * 16 + (l & 3) * 2;
        uint32_t h0, l0, h1, l1;
        splitpack(W3[col * 64 + k0],     W3[col * 64 + k0 + 1], h0, l0);
        splitpack(W3[col * 64 + k0 + 8], W3[col * 64 + k0 + 9], h1, l1);
        sB3h[f * 32 + l] = make_uint2(h0, h1);
        sB3l[f * 32 + l] = make_uint2(l0, l1);
    }
    // zero K-pad words of h arrays (cols 20..31), constant across tiles
    for (int w = 10; w < 16; w++) {
        hH[tid * 16 + w] = 0u;
        hL[tid * 16 + w] = 0u;
    }
    __syncthreads();

    // hoist LSTM weights
    float rwih[32], rwhh[16], rbias[8];
#pragma unroll
    for (int i = 0; i < 32; i++) rwih[i] = sWih[i];
#pragma unroll
    for (int i = 0; i < 16; i++) rwhh[i] = sWhh[i];
#pragma unroll
    for (int i = 0; i < 8; i++)  rbias[i] = sBias[i];
    const float b4s = sb4[0];

    const int ntiles = (n + 127) >> 7;
    for (int tile = blockIdx.x; tile < ntiles; tile += gridDim.x) {
        const int row = tile * 128 + tid;
        const bool valid = (row < n);

        // ================= LSTM (1 element/thread) =================
        {
            float h0 = 0.f, h1 = 0.f, c0 = 0.f, c1 = 0.f;
            const float* xp = x + (size_t)(valid ? row : 0) * 40;
            float hv[20];
#pragma unroll
            for (int t = 0; t < 10; t++) {
                float4 xt = *reinterpret_cast<const float4*>(xp + t * 4);
                float g[8];
#pragma unroll
                for (int gi = 0; gi < 8; gi++) {
                    float a = rbias[gi];
                    a = fmaf(xt.x, rwih[gi * 4 + 0], a);
                    a = fmaf(xt.y, rwih[gi * 4 + 1], a);
                    a = fmaf(xt.z, rwih[gi * 4 + 2], a);
                    a = fmaf(xt.w, rwih[gi * 4 + 3], a);
                    a = fmaf(h0, rwhh[gi * 2 + 0], a);
                    a = fmaf(h1, rwhh[gi * 2 + 1], a);
                    g[gi] = a;
                }
                float i0 = sigf(g[0]), i1 = sigf(g[1]);
                float f0 = sigf(g[2]), f1 = sigf(g[3]);
                float g0 = tanhfast(g[4]), g1 = tanhfast(g[5]);
                float o0 = sigf(g[6]), o1 = sigf(g[7]);
                c0 = fmaf(f0, c0, i0 * g0);
                c1 = fmaf(f1, c1, i1 * g1);
                h0 = o0 * tanhfast(c0);
                h1 = o1 * tanhfast(c1);
                hv[2 * t] = h0;
                hv[2 * t + 1] = h1;
            }
            // store split h (row = tid)
#pragma unroll
            for (int i = 0; i < 10; i++) {
                uint32_t wh, wl;
                splitpack(hv[2 * i], hv[2 * i + 1], wh, wl);
                hH[tid * 16 + i] = wh;
                hL[tid * 16 + i] = wl;
            }
        }
        __syncwarp();

        // ================= MLP on tensor cores, per warp, 2 sub-tiles =================
#pragma unroll 1
        for (int s = 0; s < 2; s++) {
            const int rbase = (tid >> 5) * 32 + s * 16;
            const int r0 = rbase + (lane >> 2);

            // ---- GEMM1: [16,20pad32] x [32,128] -> c1[16 nt][4] ----
            float c1[16][4];
#pragma unroll
            for (int ntq = 0; ntq < 16; ntq++)
#pragma unroll
                for (int q = 0; q < 4; q++) c1[ntq][q] = 0.f;

#pragma unroll
            for (int kc = 0; kc < 2; kc++) {
                const int wofs = kc * 8 + (lane & 3);
                uint32_t ah[4], al[4];
                ah[0] = hH[r0 * 16 + wofs];
                ah[1] = hH[(r0 + 8) * 16 + wofs];
                ah[2] = hH[r0 * 16 + wofs + 4];
                ah[3] = hH[(r0 + 8) * 16 + wofs + 4];
                al[0] = hL[r0 * 16 + wofs];
                al[1] = hL[(r0 + 8) * 16 + wofs];
                al[2] = hL[r0 * 16 + wofs + 4];
                al[3] = hL[(r0 + 8) * 16 + wofs + 4];
#pragma unroll
                for (int ntq = 0; ntq < 16; ntq++) {
                    uint2 bh = sB1h[(kc * 16 + ntq) * 32 + lane];
                    uint2 bl = sB1l[(kc * 16 + ntq) * 32 + lane];
                    mma_bf16(c1[ntq], ah, bh);
                    mma_bf16(c1[ntq], al, bh);
                    mma_bf16(c1[ntq], ah, bl);
                }
            }

            // ---- epilogue1: bias+relu, repack as A2 fragments (8 kc) ----
            uint32_t a2h[8][4], a2l[8][4];
#pragma unroll
            for (int j = 0; j < 8; j++) {
#pragma unroll
                for (int hf = 0; hf < 2; hf++) {
                    int ntq = 2 * j + hf;
                    int col = ntq * 8 + (lane & 3) * 2;
                    float2 bb = *(const float2*)(sb1 + col);
                    float f0 = fmaxf(c1[ntq][0] + bb.x, 0.f);
                    float f1 = fmaxf(c1[ntq][1] + bb.y, 0.f);
                    float f2 = fmaxf(c1[ntq][2] + bb.x, 0.f);
                    float f3 = fmaxf(c1[ntq][3] + bb.y, 0.f);
                    splitpack(f0, f1, a2h[j][hf * 2 + 0], a2l[j][hf * 2 + 0]);
                    splitpack(f2, f3, a2h[j][hf * 2 + 1], a2l[j][hf * 2 + 1]);
                }
            }

            // ---- GEMM2: [16,128] x [128,64] -> c2[8][4] ----
            float c2[8][4];
#pragma unroll
            for (int ntq = 0; ntq < 8; ntq++)
#pragma unroll
                for (int q = 0; q < 4; q++) c2[ntq][q] = 0.f;
#pragma unroll
            for (int kc = 0; kc < 8; kc++) {
#pragma unroll
                for (int ntq = 0; ntq < 8; ntq++) {
                    uint2 bh = sB2h[(kc * 8 + ntq) * 32 + lane];
                    uint2 bl = sB2l[(kc * 8 + ntq) * 32 + lane];
                    mma_bf16(c2[ntq], a2h[kc], bh);
                    mma_bf16(c2[ntq], a2l[kc], bh);
                    mma_bf16(c2[ntq], a2h[kc], bl);
                }
            }

            // ---- epilogue2 -> A3 fragments (4 kc) ----
            uint32_t a3h[4][4], a3l[4][4];
#pragma unroll
            for (int j = 0; j < 4; j++) {
#pragma unroll
                for (int hf = 0; hf < 2; hf++) {
                    int ntq = 2 * j + hf;
                    int col = ntq * 8 + (lane & 3) * 2;
                    float2 bb = *(const float2*)(sb2 + col);
                    float f0 = fmaxf(c2[ntq][0] + bb.x, 0.f);
                    float f1 = fmaxf(c2[ntq][1] + bb.y, 0.f);
                    float f2 = fmaxf(c2[ntq][2] + bb.x, 0.f);
                    float f3 = fmaxf(c2[ntq][3] + bb.y, 0.f);
                    splitpack(f0, f1, a3h[j][hf * 2 + 0], a3l[j][hf * 2 + 0]);
                    splitpack(f2, f3, a3h[j][hf * 2 + 1], a3l[j][hf * 2 + 1]);
                }
            }

            // ---- GEMM3: [16,64] x [64,32] -> c3[4][4] ----
            float c3[4][4];
#pragma unroll
            for (int ntq = 0; ntq < 4; ntq++)
#pragma unroll
                for (int q = 0; q < 4; q++) c3[ntq][q] = 0.f;
#pragma unroll
            for (int kc = 0; kc < 4; kc++) {
#pragma unroll
                for (int ntq = 0; ntq < 4; ntq++) {
                    uint2 bh = sB3h[(kc * 4 + ntq) * 32 + lane];
                    uint2 bl = sB3l[(kc * 4 + ntq) * 32 + lane];
                    mma_bf16(c3[ntq], a3h[kc], bh);
                    mma_bf16(c3[ntq], a3l[kc], bh);
                    mma_bf16(c3[ntq], a3h[kc], bl);
                }
            }

            // ---- layer4: relu(c3+b3) . w4, reduce across quad ----
            float p0 = 0.f, p1 = 0.f;
#pragma unroll
            for (int ntq = 0; ntq < 4; ntq++) {
                int col = ntq * 8 + (lane & 3) * 2;
                float2 bb = *(const float2*)(sb3 + col);
                float2 ww = *(const float2*)(sw4 + col);
                p0 = fmaf(fmaxf(c3[ntq][0] + bb.x, 0.f), ww.x, p0);
                p0 = fmaf(fmaxf(c3[ntq][1] + bb.y, 0.f), ww.y, p0);
                p1 = fmaf(fmaxf(c3[ntq][2] + bb.x, 0.f), ww.x, p1);
                p1 = fmaf(fmaxf(c3[ntq][3] + bb.y, 0.f), ww.y, p1);
            }
            p0 += __shfl_xor_sync(0xFFFFFFFFu, p0, 1);
            p0 += __shfl_xor_sync(0xFFFFFFFFu, p0, 2);
            p1 += __shfl_xor_sync(0xFFFFFFFFu, p1, 1);
            p1 += __shfl_xor_sync(0xFFFFFFFFu, p1, 2);
            if ((lane & 3) == 0) {
                int gr = tile * 128 + rbase + (lane >> 2);
                if (gr < n)     out[gr]     = p0 + b4s;
                if (gr + 8 < n) out[gr + 8] = p1 + b4s;
            }
        }
    }
}

extern "C" void kernel_launch(void* const* d_in, const int* in_sizes, int n_in,
                              void* d_out, int out_size)
{
    const float* x    = (const float*)d_in[0];
    const float* W_ih = (const float*)d_in[1];
    const float* W_hh = (const float*)d_in[2];
    const float* b_ih = (const float*)d_in[3];
    const float* b_hh = (const float*)d_in[4];
    const float* W1   = (const float*)d_in[5];
    const float* b1   = (const float*)d_in[6];
    const float* W2   = (const float*)d_in[7];
    const float* b2   = (const float*)d_in[8];
    const float* W3   = (const float*)d_in[9];
    const float* b3   = (const float*)d_in[10];
    const float* W4   = (const float*)d_in[11];
    const float* b4   = (const float*)d_in[12];
    float* out = (float*)d_out;

    static bool attr_set = false;
    if (!attr_set) {
        cudaFuncSetAttribute(lstm_mlp_mma_kernel,
                             cudaFuncAttributeMaxDynamicSharedMemorySize, SMEM_BYTES);
        attr_set = true;
    }

    lstm_mlp_mma_kernel<<<NBLOCKS, NTHREADS, SMEM_BYTES>>>(
        x, W_ih, W_hh, b_ih, b_hh, W1, b1, W2, b2, W3, b3, W4, b4,
        out, out_size);
}

// round 9
// speedup vs baseline: 4.4335x; 1.0526x over previous
#include <cuda_runtime.h>
#include <cstdint>

#define NTHREADS 192
#define NBLOCKS  (148 * 2)
#define HSTRIDE  20   // h row stride in words -> conflict-free A loads

// ---------------- SMEM byte offsets ----------------
#define OB_B1H   0        // W1 B-frags hi: 32 frags * 32 lanes * 8B = 8192
#define OB_B1L   8192
#define OB_B2H   16384    // W2: 64 frags = 16384
#define OB_B2L   32768
#define OB_B3H   49152    // W3: 16 frags = 4096
#define OB_B3L   53248
#define OB_HHI   57344    // h hi words: 192 rows * 20 w * 4B = 15360
#define OB_HLO   72704
#define OB_b1    88064    // 128 f
#define OB_b2    88576    // 64 f
#define OB_b3    88832    // 32 f
#define OB_w4    88960    // 32 f
#define OB_b4    89088
#define OB_wih   89092    // 32 f
#define OB_whh   89220    // 16 f
#define OB_bias  89284    // 8 f
#define SMEM_BYTES 89344

// ---------------- helpers ----------------
__device__ __forceinline__ uint32_t bf16rn(float f) {
    uint32_t u = __float_as_uint(f);
    return (u + 0x7FFFu + ((u >> 16) & 1u)) >> 16;
}
// split a,b into hi word (truncated bf16 pair, a in low half) and lo word (rounded residuals)
__device__ __forceinline__ void splitpack(float a, float b, uint32_t& hi, uint32_t& lo) {
    uint32_t ua = __float_as_uint(a), ub = __float_as_uint(b);
    hi = (ub & 0xFFFF0000u) | (ua >> 16);
    float ra = a - __uint_as_float(ua & 0xFFFF0000u);
    float rb = b - __uint_as_float(ub & 0xFFFF0000u);
    lo = (bf16rn(rb) << 16) | bf16rn(ra);
}
__device__ __forceinline__ void mma_bf16(float* c, const uint32_t* a, uint2 b) {
    asm volatile(
        "mma.sync.aligned.m16n8k16.row.col.f32.bf16.bf16.f32 "
        "{%0,%1,%2,%3}, {%4,%5,%6,%7}, {%8,%9}, {%0,%1,%2,%3};"
        : "+f"(c[0]), "+f"(c[1]), "+f"(c[2]), "+f"(c[3])
        : "r"(a[0]), "r"(a[1]), "r"(a[2]), "r"(a[3]), "r"(b.x), "r"(b.y));
}
__device__ __forceinline__ float sigf(float x) {
    float e = __expf(-x);
    return __fdividef(1.0f, 1.0f + e);
}
__device__ __forceinline__ float tanhfast(float x) {
    float e = __expf(-2.0f * x);
    return __fdividef(2.0f, 1.0f + e) - 1.0f;
}

__global__ void __launch_bounds__(NTHREADS, 2)
lstm_mlp_mma_kernel(const float* __restrict__ x,
                    const float* __restrict__ W_ih, const float* __restrict__ W_hh,
                    const float* __restrict__ b_ih, const float* __restrict__ b_hh,
                    const float* __restrict__ W1, const float* __restrict__ b1,
                    const float* __restrict__ W2, const float* __restrict__ b2,
                    const float* __restrict__ W3, const float* __restrict__ b3,
                    const float* __restrict__ W4, const float* __restrict__ b4,
                    float* __restrict__ out, int n)
{
    extern __shared__ char smem[];
    const int tid  = threadIdx.x;
    const int lane = tid & 31;

    uint2* sB1h = (uint2*)(smem + OB_B1H);
    uint2* sB1l = (uint2*)(smem + OB_B1L);
    uint2* sB2h = (uint2*)(smem + OB_B2H);
    uint2* sB2l = (uint2*)(smem + OB_B2L);
    uint2* sB3h = (uint2*)(smem + OB_B3H);
    uint2* sB3l = (uint2*)(smem + OB_B3L);
    uint32_t* hH = (uint32_t*)(smem + OB_HHI);
    uint32_t* hL = (uint32_t*)(smem + OB_HLO);
    float* sb1  = (float*)(smem + OB_b1);
    float* sb2  = (float*)(smem + OB_b2);
    float* sb3  = (float*)(smem + OB_b3);
    float* sw4  = (float*)(smem + OB_w4);
    float* sb4  = (float*)(smem + OB_b4);
    float* sWih = (float*)(smem + OB_wih);
    float* sWhh = (float*)(smem + OB_whh);
    float* sBias= (float*)(smem + OB_bias);

    // ---- stage small params ----
    if (tid < 128) sb1[tid] = b1[tid];
    if (tid < 64)  sb2[tid] = b2[tid];
    if (tid < 32)  { sb3[tid] = b3[tid]; sw4[tid] = W4[tid]; }
    if (tid == 0)  sb4[0] = b4[0];
    if (tid < 32)  sWih[tid] = W_ih[tid];
    if (tid < 16)  sWhh[tid] = W_hh[tid];
    if (tid < 8)   sBias[tid] = b_ih[tid] + b_hh[tid];

    // ---- precompute B fragments (native m16n8k16 col-major B layout) ----
    // W1 [128,20], K padded to 32: 2 kc x 16 nt
    for (int e = tid; e < 32 * 32; e += NTHREADS) {
        int l = e & 31, f = e >> 5;
        int kc = f >> 4, nt = f & 15;
        int col = nt * 8 + (l >> 2);
        int k0 = kc * 16 + (l & 3) * 2;
        float v00 = (k0     < 20) ? W1[col * 20 + k0]     : 0.f;
        float v01 = (k0 + 1 < 20) ? W1[col * 20 + k0 + 1] : 0.f;
        float v10 = (k0 + 8 < 20) ? W1[col * 20 + k0 + 8] : 0.f;
        float v11 = (k0 + 9 < 20) ? W1[col * 20 + k0 + 9] : 0.f;
        uint32_t h0, l0, h1, l1;
        splitpack(v00, v01, h0, l0);
        splitpack(v10, v11, h1, l1);
        sB1h[f * 32 + l] = make_uint2(h0, h1);
        sB1l[f * 32 + l] = make_uint2(l0, l1);
    }
    // W2 [64,128]: 8 kc x 8 nt
    for (int e = tid; e < 64 * 32; e += NTHREADS) {
        int l = e & 31, f = e >> 5;
        int kc = f >> 3, nt = f & 7;
        int col = nt * 8 + (l >> 2);
        int k0 = kc * 16 + (l & 3) * 2;
        uint32_t h0, l0, h1, l1;
        splitpack(W2[col * 128 + k0],     W2[col * 128 + k0 + 1], h0, l0);
        splitpack(W2[col * 128 + k0 + 8], W2[col * 128 + k0 + 9], h1, l1);
        sB2h[f * 32 + l] = make_uint2(h0, h1);
        sB2l[f * 32 + l] = make_uint2(l0, l1);
    }
    // W3 [32,64]: 4 kc x 4 nt
    for (int e = tid; e < 16 * 32; e += NTHREADS) {
        int l = e & 31, f = e >> 5;
        int kc = f >> 2, nt = f & 3;
        int col = nt * 8 + (l >> 2);
        int k0 = kc * 16 + (l & 3) * 2;
        uint32_t h0, l0, h1, l1;
        splitpack(W3[col * 64 + k0],     W3[col * 64 + k0 + 1], h0, l0);
        splitpack(W3[col * 64 + k0 + 8], W3[col * 64 + k0 + 9], h1, l1);
        sB3h[f * 32 + l] = make_uint2(h0, h1);
        sB3l[f * 32 + l] = make_uint2(l0, l1);
    }
    // zero K-pad words of h arrays (cols 20..31 -> words 10..15), constant across tiles
#pragma unroll
    for (int w = 10; w < 16; w++) {
        hH[tid * HSTRIDE + w] = 0u;
        hL[tid * HSTRIDE + w] = 0u;
    }
    __syncthreads();

    // hoist LSTM weights
    float rwih[32], rwhh[16], rbias[8];
#pragma unroll
    for (int i = 0; i < 32; i++) rwih[i] = sWih[i];
#pragma unroll
    for (int i = 0; i < 16; i++) rwhh[i] = sWhh[i];
#pragma unroll
    for (int i = 0; i < 8; i++)  rbias[i] = sBias[i];
    const float b4s = sb4[0];

    const int ntiles = (n + NTHREADS - 1) / NTHREADS;
    for (int tile = blockIdx.x; tile < ntiles; tile += gridDim.x) {
        const int row = tile * NTHREADS + tid;
        const bool valid = (row < n);

        // ================= LSTM (1 element/thread) =================
        {
            float h0 = 0.f, h1 = 0.f, c0 = 0.f, c1 = 0.f;
            const float* xp = x + (size_t)(valid ? row : 0) * 40;
            float hv[20];
#pragma unroll
            for (int t = 0; t < 10; t++) {
                float4 xt = *reinterpret_cast<const float4*>(xp + t * 4);
                float g[8];
#pragma unroll
                for (int gi = 0; gi < 8; gi++) {
                    float a = rbias[gi];
                    a = fmaf(xt.x, rwih[gi * 4 + 0], a);
                    a = fmaf(xt.y, rwih[gi * 4 + 1], a);
                    a = fmaf(xt.z, rwih[gi * 4 + 2], a);
                    a = fmaf(xt.w, rwih[gi * 4 + 3], a);
                    a = fmaf(h0, rwhh[gi * 2 + 0], a);
                    a = fmaf(h1, rwhh[gi * 2 + 1], a);
                    g[gi] = a;
                }
                float i0 = sigf(g[0]), i1 = sigf(g[1]);
                float f0 = sigf(g[2]), f1 = sigf(g[3]);
                float g0 = tanhfast(g[4]), g1 = tanhfast(g[5]);
                float o0 = sigf(g[6]), o1 = sigf(g[7]);
                c0 = fmaf(f0, c0, i0 * g0);
                c1 = fmaf(f1, c1, i1 * g1);
                h0 = o0 * tanhfast(c0);
                h1 = o1 * tanhfast(c1);
                hv[2 * t] = h0;
                hv[2 * t + 1] = h1;
            }
            // store split h (row = tid)
#pragma unroll
            for (int i = 0; i < 10; i++) {
                uint32_t wh, wl;
                splitpack(hv[2 * i], hv[2 * i + 1], wh, wl);
                hH[tid * HSTRIDE + i] = wh;
                hL[tid * HSTRIDE + i] = wl;
            }
        }
        __syncwarp();

        // ================= MLP on tensor cores, per warp, 2 sub-tiles =================
#pragma unroll 1
        for (int s = 0; s < 2; s++) {
            const int rbase = (tid >> 5) * 32 + s * 16;
            const int r0 = rbase + (lane >> 2);

            // ---- A1 fragments for both kc (conflict-free stride-20 loads) ----
            uint32_t ah[2][4], al[2][4];
#pragma unroll
            for (int kc = 0; kc < 2; kc++) {
                const int wofs = kc * 8 + (lane & 3);
                ah[kc][0] = hH[r0 * HSTRIDE + wofs];
                ah[kc][1] = hH[(r0 + 8) * HSTRIDE + wofs];
                ah[kc][2] = hH[r0 * HSTRIDE + wofs + 4];
                ah[kc][3] = hH[(r0 + 8) * HSTRIDE + wofs + 4];
                al[kc][0] = hL[r0 * HSTRIDE + wofs];
                al[kc][1] = hL[(r0 + 8) * HSTRIDE + wofs];
                al[kc][2] = hL[r0 * HSTRIDE + wofs + 4];
                al[kc][3] = hL[(r0 + 8) * HSTRIDE + wofs + 4];
            }

            // ---- GEMM1 fused with epilogue1: per n-tile -> A2 fragments ----
            uint32_t a2h[8][4], a2l[8][4];
#pragma unroll
            for (int j = 0; j < 8; j++) {
#pragma unroll
                for (int hf = 0; hf < 2; hf++) {
                    const int ntq = 2 * j + hf;
                    float c[4] = {0.f, 0.f, 0.f, 0.f};
#pragma unroll
                    for (int kc = 0; kc < 2; kc++) {
                        uint2 bh = sB1h[(kc * 16 + ntq) * 32 + lane];
                        uint2 bl = sB1l[(kc * 16 + ntq) * 32 + lane];
                        mma_bf16(c, ah[kc], bh);
                        mma_bf16(c, al[kc], bh);
                        mma_bf16(c, ah[kc], bl);
                    }
                    int col = ntq * 8 + (lane & 3) * 2;
                    float2 bb = *(const float2*)(sb1 + col);
                    float f0 = fmaxf(c[0] + bb.x, 0.f);
                    float f1 = fmaxf(c[1] + bb.y, 0.f);
                    float f2 = fmaxf(c[2] + bb.x, 0.f);
                    float f3 = fmaxf(c[3] + bb.y, 0.f);
                    splitpack(f0, f1, a2h[j][hf * 2 + 0], a2l[j][hf * 2 + 0]);
                    splitpack(f2, f3, a2h[j][hf * 2 + 1], a2l[j][hf * 2 + 1]);
                }
            }

            // ---- GEMM2: [16,128] x [128,64] -> c2[8][4] (kc-outer for ILP) ----
            float c2[8][4];
#pragma unroll
            for (int ntq = 0; ntq < 8; ntq++)
#pragma unroll
                for (int q = 0; q < 4; q++) c2[ntq][q] = 0.f;
#pragma unroll
            for (int kc = 0; kc < 8; kc++) {
#pragma unroll
                for (int ntq = 0; ntq < 8; ntq++) {
                    uint2 bh = sB2h[(kc * 8 + ntq) * 32 + lane];
                    uint2 bl = sB2l[(kc * 8 + ntq) * 32 + lane];
                    mma_bf16(c2[ntq], a2h[kc], bh);
                    mma_bf16(c2[ntq], a2l[kc], bh);
                    mma_bf16(c2[ntq], a2h[kc], bl);
                }
            }

            // ---- epilogue2 -> A3 fragments (4 kc) ----
            uint32_t a3h[4][4], a3l[4][4];
#pragma unroll
            for (int j = 0; j < 4; j++) {
#pragma unroll
                for (int hf = 0; hf < 2; hf++) {
                    int ntq = 2 * j + hf;
                    int col = ntq * 8 + (lane & 3) * 2;
                    float2 bb = *(const float2*)(sb2 + col);
                    float f0 = fmaxf(c2[ntq][0] + bb.x, 0.f);
                    float f1 = fmaxf(c2[ntq][1] + bb.y, 0.f);
                    float f2 = fmaxf(c2[ntq][2] + bb.x, 0.f);
                    float f3 = fmaxf(c2[ntq][3] + bb.y, 0.f);
                    splitpack(f0, f1, a3h[j][hf * 2 + 0], a3l[j][hf * 2 + 0]);
                    splitpack(f2, f3, a3h[j][hf * 2 + 1], a3l[j][hf * 2 + 1]);
                }
            }

            // ---- GEMM3: [16,64] x [64,32] -> c3[4][4] ----
            float c3[4][4];
#pragma unroll
            for (int ntq = 0; ntq < 4; ntq++)
#pragma unroll
                for (int q = 0; q < 4; q++) c3[ntq][q] = 0.f;
#pragma unroll
            for (int kc = 0; kc < 4; kc++) {
#pragma unroll
                for (int ntq = 0; ntq < 4; ntq++) {
                    uint2 bh = sB3h[(kc * 4 + ntq) * 32 + lane];
                    uint2 bl = sB3l[(kc * 4 + ntq) * 32 + lane];
                    mma_bf16(c3[ntq], a3h[kc], bh);
                    mma_bf16(c3[ntq], a3l[kc], bh);
                    mma_bf16(c3[ntq], a3h[kc], bl);
                }
            }

            // ---- layer4: relu(c3+b3) . w4, reduce across quad ----
            float p0 = 0.f, p1 = 0.f;
#pragma unroll
            for (int ntq = 0; ntq < 4; ntq++) {
                int col = ntq * 8 + (lane & 3) * 2;
                float2 bb = *(const float2*)(sb3 + col);
                float2 ww = *(const float2*)(sw4 + col);
                p0 = fmaf(fmaxf(c3[ntq][0] + bb.x, 0.f), ww.x, p0);
                p0 = fmaf(fmaxf(c3[ntq][1] + bb.y, 0.f), ww.y, p0);
                p1 = fmaf(fmaxf(c3[ntq][2] + bb.x, 0.f), ww.x, p1);
                p1 = fmaf(fmaxf(c3[ntq][3] + bb.y, 0.f), ww.y, p1);
            }
            p0 += __shfl_xor_sync(0xFFFFFFFFu, p0, 1);
            p0 += __shfl_xor_sync(0xFFFFFFFFu, p0, 2);
            p1 += __shfl_xor_sync(0xFFFFFFFFu, p1, 1);
            p1 += __shfl_xor_sync(0xFFFFFFFFu, p1, 2);
            if ((lane & 3) == 0) {
                int gr = tile * NTHREADS + rbase + (lane >> 2);
                if (gr < n)     out[gr]     = p0 + b4s;
                if (gr + 8 < n) out[gr + 8] = p1 + b4s;
            }
        }
    }
}

extern "C" void kernel_launch(void* const* d_in, const int* in_sizes, int n_in,
                              void* d_out, int out_size)
{
    const float* x    = (const float*)d_in[0];
    const float* W_ih = (const float*)d_in[1];
    const float* W_hh = (const float*)d_in[2];
    const float* b_ih = (const float*)d_in[3];
    const float* b_hh = (const float*)d_in[4];
    const float* W1   = (const float*)d_in[5];
    const float* b1   = (const float*)d_in[6];
    const float* W2   = (const float*)d_in[7];
    const float* b2   = (const float*)d_in[8];
    const float* W3   = (const float*)d_in[9];
    const float* b3   = (const float*)d_in[10];
    const float* W4   = (const float*)d_in[11];
    const float* b4   = (const float*)d_in[12];
    float* out = (float*)d_out;

    static bool attr_set = false;
    if (!attr_set) {
        cudaFuncSetAttribute(lstm_mlp_mma_kernel,
                             cudaFuncAttributeMaxDynamicSharedMemorySize, SMEM_BYTES);
        attr_set = true;
    }

    lstm_mlp_mma_kernel<<<NBLOCKS, NTHREADS, SMEM_BYTES>>>(
        x, W_ih, W_hh, b_ih, b_hh, W1, b1, W2, b2, W3, b3, W4, b4,
        out, out_size);
}

// round 10
// speedup vs baseline: 4.4719x; 1.0087x over previous
#include <cuda_runtime.h>
#include <cstdint>

#define NTHREADS 192
#define NBLOCKS  (148 * 2)
#define HSTRIDE  20   // h row stride in words -> conflict-free A loads

// ---------------- SMEM byte offsets ----------------
#define OB_B1H   0        // W1 B-frags hi: 32 frags * 32 lanes * 8B = 8192
#define OB_B1L   8192
#define OB_B2H   16384    // W2: 64 frags = 16384
#define OB_B2L   32768
#define OB_B3H   49152    // W3: 16 frags = 4096
#define OB_B3L   53248
#define OB_HHI   57344    // h hi words: 192 rows * 20 w * 4B = 15360
#define OB_HLO   72704
#define OB_b1    88064    // 128 f
#define OB_b2    88576    // 64 f
#define OB_b3    88832    // 32 f
#define OB_w4    88960    // 32 f
#define OB_b4    89088
#define OB_wih   89092    // 32 f
#define OB_whh   89220    // 16 f
#define OB_bias  89284    // 8 f
#define SMEM_BYTES 89344

// ---------------- helpers ----------------
__device__ __forceinline__ uint32_t bf16rn(float f) {
    uint32_t u = __float_as_uint(f);
    return (u + 0x7FFFu + ((u >> 16) & 1u)) >> 16;
}
// split a,b into hi word (truncated bf16 pair, a in low half) and lo word (rounded residuals)
__device__ __forceinline__ void splitpack(float a, float b, uint32_t& hi, uint32_t& lo) {
    uint32_t ua = __float_as_uint(a), ub = __float_as_uint(b);
    hi = (ub & 0xFFFF0000u) | (ua >> 16);
    float ra = a - __uint_as_float(ua & 0xFFFF0000u);
    float rb = b - __uint_as_float(ub & 0xFFFF0000u);
    lo = (bf16rn(rb) << 16) | bf16rn(ra);
}
__device__ __forceinline__ void mma_bf16(float* c, const uint32_t* a, uint2 b) {
    asm volatile(
        "mma.sync.aligned.m16n8k16.row.col.f32.bf16.bf16.f32 "
        "{%0,%1,%2,%3}, {%4,%5,%6,%7}, {%8,%9}, {%0,%1,%2,%3};"
        : "+f"(c[0]), "+f"(c[1]), "+f"(c[2]), "+f"(c[3])
        : "r"(a[0]), "r"(a[1]), "r"(a[2]), "r"(a[3]), "r"(b.x), "r"(b.y));
}
__device__ __forceinline__ float sigf(float x) {
    float e = __expf(-x);
    return __fdividef(1.0f, 1.0f + e);
}
__device__ __forceinline__ float tanhfast(float x) {
    float e = __expf(-2.0f * x);
    return __fdividef(2.0f, 1.0f + e) - 1.0f;
}

__global__ void __launch_bounds__(NTHREADS, 2)
lstm_mlp_mma_kernel(const float* __restrict__ x,
                    const float* __restrict__ W_ih, const float* __restrict__ W_hh,
                    const float* __restrict__ b_ih, const float* __restrict__ b_hh,
                    const float* __restrict__ W1, const float* __restrict__ b1,
                    const float* __restrict__ W2, const float* __restrict__ b2,
                    const float* __restrict__ W3, const float* __restrict__ b3,
                    const float* __restrict__ W4, const float* __restrict__ b4,
                    float* __restrict__ out, int n)
{
    extern __shared__ char smem[];
    const int tid  = threadIdx.x;
    const int lane = tid & 31;

    uint2* sB1h = (uint2*)(smem + OB_B1H);
    uint2* sB1l = (uint2*)(smem + OB_B1L);
    uint2* sB2h = (uint2*)(smem + OB_B2H);
    uint2* sB2l = (uint2*)(smem + OB_B2L);
    uint2* sB3h = (uint2*)(smem + OB_B3H);
    uint2* sB3l = (uint2*)(smem + OB_B3L);
    uint32_t* hH = (uint32_t*)(smem + OB_HHI);
    uint32_t* hL = (uint32_t*)(smem + OB_HLO);
    float* sb1  = (float*)(smem + OB_b1);
    float* sb2  = (float*)(smem + OB_b2);
    float* sb3  = (float*)(smem + OB_b3);
    float* sw4  = (float*)(smem + OB_w4);
    float* sb4  = (float*)(smem + OB_b4);
    float* sWih = (float*)(smem + OB_wih);
    float* sWhh = (float*)(smem + OB_whh);
    float* sBias= (float*)(smem + OB_bias);

    // ---- stage small params ----
    if (tid < 128) sb1[tid] = b1[tid];
    if (tid < 64)  sb2[tid] = b2[tid];
    if (tid < 32)  { sb3[tid] = b3[tid]; sw4[tid] = W4[tid]; }
    if (tid == 0)  sb4[0] = b4[0];
    if (tid < 32)  sWih[tid] = W_ih[tid];
    if (tid < 16)  sWhh[tid] = W_hh[tid];
    if (tid < 8)   sBias[tid] = b_ih[tid] + b_hh[tid];

    // ---- precompute B fragments (native m16n8k16 col-major B layout) ----
    // W1 [128,20], K padded to 32: 2 kc x 16 nt
    for (int e = tid; e < 32 * 32; e += NTHREADS) {
        int l = e & 31, f = e >> 5;
        int kc = f >> 4, nt = f & 15;
        int col = nt * 8 + (l >> 2);
        int k0 = kc * 16 + (l & 3) * 2;
        float v00 = (k0     < 20) ? W1[col * 20 + k0]     : 0.f;
        float v01 = (k0 + 1 < 20) ? W1[col * 20 + k0 + 1] : 0.f;
        float v10 = (k0 + 8 < 20) ? W1[col * 20 + k0 + 8] : 0.f;
        float v11 = (k0 + 9 < 20) ? W1[col * 20 + k0 + 9] : 0.f;
        uint32_t h0, l0, h1, l1;
        splitpack(v00, v01, h0, l0);
        splitpack(v10, v11, h1, l1);
        sB1h[f * 32 + l] = make_uint2(h0, h1);
        sB1l[f * 32 + l] = make_uint2(l0, l1);
    }
    // W2 [64,128]: 8 kc x 8 nt
    for (int e = tid; e < 64 * 32; e += NTHREADS) {
        int l = e & 31, f = e >> 5;
        int kc = f >> 3, nt = f & 7;
        int col = nt * 8 + (l >> 2);
        int k0 = kc * 16 + (l & 3) * 2;
        uint32_t h0, l0, h1, l1;
        splitpack(W2[col * 128 + k0],     W2[col * 128 + k0 + 1], h0, l0);
        splitpack(W2[col * 128 + k0 + 8], W2[col * 128 + k0 + 9], h1, l1);
        sB2h[f * 32 + l] = make_uint2(h0, h1);
        sB2l[f * 32 + l] = make_uint2(l0, l1);
    }
    // W3 [32,64]: 4 kc x 4 nt
    for (int e = tid; e < 16 * 32; e += NTHREADS) {
        int l = e & 31, f = e >> 5;
        int kc = f >> 2, nt = f & 3;
        int col = nt * 8 + (l >> 2);
        int k0 = kc * 16 + (l & 3) * 2;
        uint32_t h0, l0, h1, l1;
        splitpack(W3[col * 64 + k0],     W3[col * 64 + k0 + 1], h0, l0);
        splitpack(W3[col * 64 + k0 + 8], W3[col * 64 + k0 + 9], h1, l1);
        sB3h[f * 32 + l] = make_uint2(h0, h1);
        sB3l[f * 32 + l] = make_uint2(l0, l1);
    }
    // zero K-pad words of h arrays (cols 20..31 -> words 10..15), constant across tiles
#pragma unroll
    for (int w = 10; w < 16; w++) {
        hH[tid * HSTRIDE + w] = 0u;
        hL[tid * HSTRIDE + w] = 0u;
    }
    __syncthreads();

    // hoist LSTM weights
    float rwih[32], rwhh[16], rbias[8];
#pragma unroll
    for (int i = 0; i < 32; i++) rwih[i] = sWih[i];
#pragma unroll
    for (int i = 0; i < 16; i++) rwhh[i] = sWhh[i];
#pragma unroll
    for (int i = 0; i < 8; i++)  rbias[i] = sBias[i];
    const float b4s = sb4[0];

    const int ntiles = (n + NTHREADS - 1) / NTHREADS;
    for (int tile = blockIdx.x; tile < ntiles; tile += gridDim.x) {
        const int row = tile * NTHREADS + tid;
        const bool valid = (row < n);

        // ================= LSTM (1 element/thread) =================
        {
            float h0 = 0.f, h1 = 0.f, c0 = 0.f, c1 = 0.f;
            const float* xp = x + (size_t)(valid ? row : 0) * 40;
            float hv[20];
#pragma unroll
            for (int t = 0; t < 10; t++) {
                float4 xt = *reinterpret_cast<const float4*>(xp + t * 4);
                float g[8];
#pragma unroll
                for (int gi = 0; gi < 8; gi++) {
                    float a = rbias[gi];
                    a = fmaf(xt.x, rwih[gi * 4 + 0], a);
                    a = fmaf(xt.y, rwih[gi * 4 + 1], a);
                    a = fmaf(xt.z, rwih[gi * 4 + 2], a);
                    a = fmaf(xt.w, rwih[gi * 4 + 3], a);
                    a = fmaf(h0, rwhh[gi * 2 + 0], a);
                    a = fmaf(h1, rwhh[gi * 2 + 1], a);
                    g[gi] = a;
                }
                float i0 = sigf(g[0]), i1 = sigf(g[1]);
                float f0 = sigf(g[2]), f1 = sigf(g[3]);
                float g0 = tanhfast(g[4]), g1 = tanhfast(g[5]);
                float o0 = sigf(g[6]), o1 = sigf(g[7]);
                c0 = fmaf(f0, c0, i0 * g0);
                c1 = fmaf(f1, c1, i1 * g1);
                h0 = o0 * tanhfast(c0);
                h1 = o1 * tanhfast(c1);
                hv[2 * t] = h0;
                hv[2 * t + 1] = h1;
            }
            // store split h (row = tid)
#pragma unroll
            for (int i = 0; i < 10; i++) {
                uint32_t wh, wl;
                splitpack(hv[2 * i], hv[2 * i + 1], wh, wl);
                hH[tid * HSTRIDE + i] = wh;
                hL[tid * HSTRIDE + i] = wl;
            }
        }
        __syncwarp();

        // ================= MLP on tensor cores, per warp, 2 sub-tiles =================
#pragma unroll 1
        for (int s = 0; s < 2; s++) {
            const int rbase = (tid >> 5) * 32 + s * 16;
            const int r0 = rbase + (lane >> 2);

            // ---- A1 fragments for both kc (conflict-free stride-20 loads) ----
            uint32_t ah[2][4], al[2][4];
#pragma unroll
            for (int kc = 0; kc < 2; kc++) {
                const int wofs = kc * 8 + (lane & 3);
                ah[kc][0] = hH[r0 * HSTRIDE + wofs];
                ah[kc][1] = hH[(r0 + 8) * HSTRIDE + wofs];
                ah[kc][2] = hH[r0 * HSTRIDE + wofs + 4];
                ah[kc][3] = hH[(r0 + 8) * HSTRIDE + wofs + 4];
                al[kc][0] = hL[r0 * HSTRIDE + wofs];
                al[kc][1] = hL[(r0 + 8) * HSTRIDE + wofs];
                al[kc][2] = hL[r0 * HSTRIDE + wofs + 4];
                al[kc][3] = hL[(r0 + 8) * HSTRIDE + wofs + 4];
            }

            // ---- GEMM1 (groups of 4 n-tiles, interleaved mma) + fused epilogue1 ----
            uint32_t a2h[8][4], a2l[8][4];
#pragma unroll
            for (int g = 0; g < 4; g++) {
                float c[4][4];
#pragma unroll
                for (int q = 0; q < 4; q++)
#pragma unroll
                    for (int e = 0; e < 4; e++) c[q][e] = 0.f;
#pragma unroll
                for (int kc = 0; kc < 2; kc++) {
                    uint2 bh[4], bl[4];
#pragma unroll
                    for (int q = 0; q < 4; q++) {
                        bh[q] = sB1h[(kc * 16 + 4 * g + q) * 32 + lane];
                        bl[q] = sB1l[(kc * 16 + 4 * g + q) * 32 + lane];
                    }
#pragma unroll
                    for (int q = 0; q < 4; q++) mma_bf16(c[q], ah[kc], bh[q]);
#pragma unroll
                    for (int q = 0; q < 4; q++) mma_bf16(c[q], al[kc], bh[q]);
#pragma unroll
                    for (int q = 0; q < 4; q++) mma_bf16(c[q], ah[kc], bl[q]);
                }
                // epilogue1 for these 4 n-tiles
#pragma unroll
                for (int q = 0; q < 4; q++) {
                    const int ntq = 4 * g + q;
                    const int j = ntq >> 1, hf = ntq & 1;
                    int col = ntq * 8 + (lane & 3) * 2;
                    float2 bb = *(const float2*)(sb1 + col);
                    float f0 = fmaxf(c[q][0] + bb.x, 0.f);
                    float f1 = fmaxf(c[q][1] + bb.y, 0.f);
                    float f2 = fmaxf(c[q][2] + bb.x, 0.f);
                    float f3 = fmaxf(c[q][3] + bb.y, 0.f);
                    splitpack(f0, f1, a2h[j][hf * 2 + 0], a2l[j][hf * 2 + 0]);
                    splitpack(f2, f3, a2h[j][hf * 2 + 1], a2l[j][hf * 2 + 1]);
                }
            }

            // ---- GEMM2: [16,128] x [128,64]; term-major, 8-way interleave ----
            float c2[8][4];
#pragma unroll
            for (int ntq = 0; ntq < 8; ntq++)
#pragma unroll
                for (int q = 0; q < 4; q++) c2[ntq][q] = 0.f;
#pragma unroll
            for (int kc = 0; kc < 8; kc++) {
                uint2 bh[8];
#pragma unroll
                for (int q = 0; q < 8; q++) bh[q] = sB2h[(kc * 8 + q) * 32 + lane];
#pragma unroll
                for (int q = 0; q < 8; q++) mma_bf16(c2[q], a2h[kc], bh[q]);
#pragma unroll
                for (int q = 0; q < 8; q++) mma_bf16(c2[q], a2l[kc], bh[q]);
#pragma unroll
                for (int q = 0; q < 8; q++) {
                    uint2 bl = sB2l[(kc * 8 + q) * 32 + lane];
                    mma_bf16(c2[q], a2h[kc], bl);
                }
            }

            // ---- epilogue2 -> A3 fragments (4 kc) ----
            uint32_t a3h[4][4], a3l[4][4];
#pragma unroll
            for (int j = 0; j < 4; j++) {
#pragma unroll
                for (int hf = 0; hf < 2; hf++) {
                    int ntq = 2 * j + hf;
                    int col = ntq * 8 + (lane & 3) * 2;
                    float2 bb = *(const float2*)(sb2 + col);
                    float f0 = fmaxf(c2[ntq][0] + bb.x, 0.f);
                    float f1 = fmaxf(c2[ntq][1] + bb.y, 0.f);
                    float f2 = fmaxf(c2[ntq][2] + bb.x, 0.f);
                    float f3 = fmaxf(c2[ntq][3] + bb.y, 0.f);
                    splitpack(f0, f1, a3h[j][hf * 2 + 0], a3l[j][hf * 2 + 0]);
                    splitpack(f2, f3, a3h[j][hf * 2 + 1], a3l[j][hf * 2 + 1]);
                }
            }

            // ---- GEMM3: [16,64] x [64,32]; term-major, 4-way interleave ----
            float c3[4][4];
#pragma unroll
            for (int ntq = 0; ntq < 4; ntq++)
#pragma unroll
                for (int q = 0; q < 4; q++) c3[ntq][q] = 0.f;
#pragma unroll
            for (int kc = 0; kc < 4; kc++) {
                uint2 bh[4];
#pragma unroll
                for (int q = 0; q < 4; q++) bh[q] = sB3h[(kc * 4 + q) * 32 + lane];
#pragma unroll
                for (int q = 0; q < 4; q++) mma_bf16(c3[q], a3h[kc], bh[q]);
#pragma unroll
                for (int q = 0; q < 4; q++) mma_bf16(c3[q], a3l[kc], bh[q]);
#pragma unroll
                for (int q = 0; q < 4; q++) {
                    uint2 bl = sB3l[(kc * 4 + q) * 32 + lane];
                    mma_bf16(c3[q], a3h[kc], bl);
                }
            }

            // ---- layer4: relu(c3+b3) . w4, reduce across quad ----
            float p0 = 0.f, p1 = 0.f;
#pragma unroll
            for (int ntq = 0; ntq < 4; ntq++) {
                int col = ntq * 8 + (lane & 3) * 2;
                float2 bb = *(const float2*)(sb3 + col);
                float2 ww = *(const float2*)(sw4 + col);
                p0 = fmaf(fmaxf(c3[ntq][0] + bb.x, 0.f), ww.x, p0);
                p0 = fmaf(fmaxf(c3[ntq][1] + bb.y, 0.f), ww.y, p0);
                p1 = fmaf(fmaxf(c3[ntq][2] + bb.x, 0.f), ww.x, p1);
                p1 = fmaf(fmaxf(c3[ntq][3] + bb.y, 0.f), ww.y, p1);
            }
            p0 += __shfl_xor_sync(0xFFFFFFFFu, p0, 1);
            p0 += __shfl_xor_sync(0xFFFFFFFFu, p0, 2);
            p1 += __shfl_xor_sync(0xFFFFFFFFu, p1, 1);
            p1 += __shfl_xor_sync(0xFFFFFFFFu, p1, 2);
            if ((lane & 3) == 0) {
                int gr = tile * NTHREADS + rbase + (lane >> 2);
                if (gr < n)     out[gr]     = p0 + b4s;
                if (gr + 8 < n) out[gr + 8] = p1 + b4s;
            }
        }
    }
}

extern "C" void kernel_launch(void* const* d_in, const int* in_sizes, int n_in,
                              void* d_out, int out_size)
{
    const float* x    = (const float*)d_in[0];
    const float* W_ih = (const float*)d_in[1];
    const float* W_hh = (const float*)d_in[2];
    const float* b_ih = (const float*)d_in[3];
    const float* b_hh = (const float*)d_in[4];
    const float* W1   = (const float*)d_in[5];
    const float* b1   = (const float*)d_in[6];
    const float* W2   = (const float*)d_in[7];
    const float* b2   = (const float*)d_in[8];
    const float* W3   = (const float*)d_in[9];
    const float* b3   = (const float*)d_in[10];
    const float* W4   = (const float*)d_in[11];
    const float* b4   = (const float*)d_in[12];
    float* out = (float*)d_out;

    static bool attr_set = false;
    if (!attr_set) {
        cudaFuncSetAttribute(lstm_mlp_mma_kernel,
                             cudaFuncAttributeMaxDynamicSharedMemorySize, SMEM_BYTES);
        attr_set = true;
    }

    lstm_mlp_mma_kernel<<<NBLOCKS, NTHREADS, SMEM_BYTES>>>(
        x, W_ih, W_hh, b_ih, b_hh, W1, b1, W2, b2, W3, b3, W4, b4,
        out, out_size);
}